// round 12
// baseline (speedup 1.0000x reference)
#include <cuda_runtime.h>
#include <math.h>

#define K 4
#define N 4096
#define D 256
#define S 32
#define MAXDEG 512
#define ETA 0.5f
#define COEFF 0.03125f   // S/(N*EPS^2)

// ---------------- scratch ----------------
__device__ float g_Zt[K * N * S];        // [k][n][s]
__device__ float g_MZt[K * N * S];       // [k][n][s]
__device__ float g_Minv[K * S * S];
__device__ float g_O[(size_t)N * (K * S)];   // O_cat: [n][k*S+s]
__device__ float g_O2[(size_t)N * (K * S)];  // (I - lam*L) @ O_cat
__device__ float g_Wc[K * S * D];        // w_k * U[k]^T : [k*S+s][d]
__device__ float g_gramP[K * 64 * S * S];
__device__ int   g_col[(size_t)N * MAXDEG];
__device__ int   g_deg[N];
__device__ float g_partials[N];
__device__ float g_orth[10];
__device__ int   g_ctr;       // zero-init; self-resetting
__device__ int   g_ctrK[K];   // zero-init; self-resetting

__device__ __forceinline__ float warpSum(float v) {
    v += __shfl_xor_sync(0xffffffffu, v, 16);
    v += __shfl_xor_sync(0xffffffffu, v, 8);
    v += __shfl_xor_sync(0xffffffffu, v, 4);
    v += __shfl_xor_sync(0xffffffffu, v, 2);
    v += __shfl_xor_sync(0xffffffffu, v, 1);
    return v;
}

// ================= mega kernel 1 =================
// blocks 0..255   : Z GEMM (64 rows each) + 64-row Gram partial + last-per-k GJ inversion
// blocks 256..767 : CSR build
// blocks 768..799 : Wc prep
// blocks 800..809 : orth pairs
__global__ void __launch_bounds__(256) k_mega1(const float* __restrict__ hops,
                                               const float* __restrict__ adj,
                                               const float* __restrict__ U,
                                               const float* __restrict__ hw) {
    __shared__ float sm[6528];
    __shared__ int isLast;
    int bx = blockIdx.x;
    int tid = threadIdx.x;

    if (bx < 256) {
        // ---------- Z = hops[k] @ U[k] : 64n x 32s tile, double-buffered ----------
        int k = bx >> 6;
        int chunkIdx = bx & 63;
        int n0 = chunkIdx * 64;
        float* hsT0 = sm;            // 32*66
        float* hsT1 = sm + 2112;
        float* us0  = sm + 4224;     // 32*36
        float* us1  = sm + 5376;
        int ny = tid >> 3;
        int sx = (tid & 7) * 4;
        int rowq = tid >> 3;
        int q = tid & 7;
        const float* Hb = hops + ((size_t)k * N + n0) * D;
        const float* Ub = U + (size_t)k * D * S;

        float4 h0, h1, u0;
        h0 = *(const float4*)&Hb[(size_t)rowq * D + q * 4];
        h1 = *(const float4*)&Hb[(size_t)(rowq + 32) * D + q * 4];
        u0 = *(const float4*)&Ub[(size_t)rowq * S + q * 4];
        {
            float* hb = hsT0;
            hb[(q * 4 + 0) * 66 + rowq] = h0.x;
            hb[(q * 4 + 1) * 66 + rowq] = h0.y;
            hb[(q * 4 + 2) * 66 + rowq] = h0.z;
            hb[(q * 4 + 3) * 66 + rowq] = h0.w;
            hb[(q * 4 + 0) * 66 + rowq + 32] = h1.x;
            hb[(q * 4 + 1) * 66 + rowq + 32] = h1.y;
            hb[(q * 4 + 2) * 66 + rowq + 32] = h1.z;
            hb[(q * 4 + 3) * 66 + rowq + 32] = h1.w;
            *(float4*)&us0[rowq * 36 + q * 4] = u0;
        }
        __syncthreads();

        float a0x = 0.f, a0y = 0.f, a0z = 0.f, a0w = 0.f;
        float a1x = 0.f, a1y = 0.f, a1z = 0.f, a1w = 0.f;

        for (int ch = 0; ch < 8; ch++) {
            const float* hb = (ch & 1) ? hsT1 : hsT0;
            const float* ub = (ch & 1) ? us1 : us0;
            if (ch < 7) {
                int dc = (ch + 1) * 32;
                h0 = *(const float4*)&Hb[(size_t)rowq * D + dc + q * 4];
                h1 = *(const float4*)&Hb[(size_t)(rowq + 32) * D + dc + q * 4];
                u0 = *(const float4*)&Ub[(size_t)(dc + rowq) * S + q * 4];
            }
#pragma unroll
            for (int d = 0; d < 32; d++) {
                float2 h = *(const float2*)&hb[d * 66 + ny * 2];
                float4 u = *(const float4*)&ub[d * 36 + sx];
                a0x += h.x * u.x; a0y += h.x * u.y; a0z += h.x * u.z; a0w += h.x * u.w;
                a1x += h.y * u.x; a1y += h.y * u.y; a1z += h.y * u.z; a1w += h.y * u.w;
            }
            if (ch < 7) {
                float* hb2 = (ch & 1) ? hsT0 : hsT1;
                float* ub2 = (ch & 1) ? us0 : us1;
                hb2[(q * 4 + 0) * 66 + rowq] = h0.x;
                hb2[(q * 4 + 1) * 66 + rowq] = h0.y;
                hb2[(q * 4 + 2) * 66 + rowq] = h0.z;
                hb2[(q * 4 + 3) * 66 + rowq] = h0.w;
                hb2[(q * 4 + 0) * 66 + rowq + 32] = h1.x;
                hb2[(q * 4 + 1) * 66 + rowq + 32] = h1.y;
                hb2[(q * 4 + 2) * 66 + rowq + 32] = h1.z;
                hb2[(q * 4 + 3) * 66 + rowq + 32] = h1.w;
                *(float4*)&ub2[rowq * 36 + q * 4] = u0;
            }
            __syncthreads();
        }
        size_t base = ((size_t)k * N + n0 + ny * 2) * S + sx;
        *(float4*)&g_Zt[base] = make_float4(a0x, a0y, a0z, a0w);
        *(float4*)&g_Zt[base + S] = make_float4(a1x, a1y, a1z, a1w);

        // ---------- Gram partial from the register-resident Z tile ----------
        float* zs = sm;   // 64 x 36 (hsT dead after final syncthreads)
        *(float4*)&zs[(ny * 2) * 36 + sx] = make_float4(a0x, a0y, a0z, a0w);
        *(float4*)&zs[(ny * 2 + 1) * 36 + sx] = make_float4(a1x, a1y, a1z, a1w);
        __syncthreads();
        int t = tid & 31;
        int w8 = tid >> 5;     // warp id 0..7 -> s rows {w8, w8+8, w8+16, w8+24}
        float g0 = 0.f, g1 = 0.f, g2 = 0.f, g3 = 0.f;
#pragma unroll 4
        for (int nn = 0; nn < 64; nn++) {
            float zt = zs[nn * 36 + t];
            g0 += zs[nn * 36 + w8] * zt;
            g1 += zs[nn * 36 + w8 + 8] * zt;
            g2 += zs[nn * 36 + w8 + 16] * zt;
            g3 += zs[nn * 36 + w8 + 24] * zt;
        }
        size_t gb = (size_t)(k * 64 + chunkIdx) * S * S;
        g_gramP[gb + (w8) * S + t] = g0;
        g_gramP[gb + (w8 + 8) * S + t] = g1;
        g_gramP[gb + (w8 + 16) * S + t] = g2;
        g_gramP[gb + (w8 + 24) * S + t] = g3;

        __threadfence();
        if (tid == 0) {
            int v = atomicAdd(&g_ctrK[k], 1);
            isLast = (v == 63);
            if (v == 63) atomicExch(&g_ctrK[k], 0);   // self-reset for graph replay
        }
        __syncthreads();
        if (!isLast) return;
        __threadfence();

        // ---------- last block per k: sum partials + GJ inversion (256 threads) ----------
        float s0 = 0.f, s1 = 0.f, s2 = 0.f, s3 = 0.f;
        for (int c = 0; c < 64; c++) {
            size_t gc = (size_t)(k * 64 + c) * S * S;
            s0 += g_gramP[gc + w8 * S + t];
            s1 += g_gramP[gc + (w8 + 8) * S + t];
            s2 += g_gramP[gc + (w8 + 16) * S + t];
            s3 += g_gramP[gc + (w8 + 24) * S + t];
        }
        float (*aug)[66] = (float(*)[66])sm;
        __syncthreads();
        aug[w8][t]      = (w8 == t ? 1.0f : 0.0f) + COEFF * s0;
        aug[w8 + 8][t]  = (w8 + 8 == t ? 1.0f : 0.0f) + COEFF * s1;
        aug[w8 + 16][t] = (w8 + 16 == t ? 1.0f : 0.0f) + COEFF * s2;
        aug[w8 + 24][t] = (w8 + 24 == t ? 1.0f : 0.0f) + COEFF * s3;
        aug[w8][32 + t]      = (w8 == t ? 1.0f : 0.0f);
        aug[w8 + 8][32 + t]  = (w8 + 8 == t ? 1.0f : 0.0f);
        aug[w8 + 16][32 + t] = (w8 + 16 == t ? 1.0f : 0.0f);
        aug[w8 + 24][32 + t] = (w8 + 24 == t ? 1.0f : 0.0f);
        __syncthreads();

        int cc = tid & 63;
        int rbase = tid >> 6;   // 0..3; rows rbase + i*4, i=0..7
        for (int p = 0; p < 32; p++) {
            float inv = 1.0f / aug[p][p];
            float pr = aug[p][cc];
            float f[8];
#pragma unroll
            for (int i = 0; i < 8; i++) f[i] = aug[rbase + i * 4][p];
            __syncthreads();
#pragma unroll
            for (int i = 0; i < 8; i++) {
                int r = rbase + i * 4;
                if (r == p) aug[p][cc] = pr * inv;
                else        aug[r][cc] -= f[i] * inv * pr;
            }
            __syncthreads();
        }
        g_Minv[k * S * S + w8 * S + t]        = aug[w8][32 + t];
        g_Minv[k * S * S + (w8 + 8) * S + t]  = aug[w8 + 8][32 + t];
        g_Minv[k * S * S + (w8 + 16) * S + t] = aug[w8 + 16][32 + t];
        g_Minv[k * S * S + (w8 + 24) * S + t] = aug[w8 + 24][32 + t];
    } else if (bx < 768) {
        // ---------- CSR build (warp per row, float4 + 4 ballots per 128 cols) ----------
        int n = (bx - 256) * 8 + (tid >> 5);
        int lane = tid & 31;
        const float4* row = (const float4*)(adj + (size_t)n * N);
        int* dst = g_col + (size_t)n * MAXDEG;
        unsigned lm = (1u << lane) - 1u;
        int cnt = 0;
        for (int base = 0; base < N / 4; base += 32) {
            float4 a = row[base + lane];
            unsigned m0 = __ballot_sync(0xffffffffu, a.x != 0.0f);
            unsigned m1 = __ballot_sync(0xffffffffu, a.y != 0.0f);
            unsigned m2 = __ballot_sync(0xffffffffu, a.z != 0.0f);
            unsigned m3 = __ballot_sync(0xffffffffu, a.w != 0.0f);
            int pre = cnt + __popc(m0 & lm) + __popc(m1 & lm)
                          + __popc(m2 & lm) + __popc(m3 & lm);
            int j0 = (base + lane) * 4;
            if (a.x != 0.0f) dst[pre] = j0;
            int o1 = pre + ((m0 >> lane) & 1);
            if (a.y != 0.0f) dst[o1] = j0 + 1;
            int o2 = o1 + ((m1 >> lane) & 1);
            if (a.z != 0.0f) dst[o2] = j0 + 2;
            int o3 = o2 + ((m2 >> lane) & 1);
            if (a.w != 0.0f) dst[o3] = j0 + 3;
            cnt += __popc(m0) + __popc(m1) + __popc(m2) + __popc(m3);
        }
        if (lane == 0) g_deg[n] = min(cnt, MAXDEG);
    } else if (bx < 800) {
        // ---------- Wc[k*S+s][d] = w_k * U[k][d][s] ----------
        float m = fmaxf(fmaxf(hw[0], hw[1]), fmaxf(hw[2], hw[3]));
        float e0 = expf(hw[0] - m), e1 = expf(hw[1] - m);
        float e2 = expf(hw[2] - m), e3 = expf(hw[3] - m);
        float sum = e0 + e1 + e2 + e3;
        int base = ((bx - 768) * 256 + tid) * 4;
        float4 u4 = *(const float4*)&U[base];
        int k = base / (D * S);
        int rem = base % (D * S);
        int d = rem / S;
        int s = rem % S;
        float wk = (k == 0 ? e0 : k == 1 ? e1 : k == 2 ? e2 : e3) / sum;
        g_Wc[(k * S + s + 0) * D + d] = wk * u4.x;
        g_Wc[(k * S + s + 1) * D + d] = wk * u4.y;
        g_Wc[(k * S + s + 2) * D + d] = wk * u4.z;
        g_Wc[(k * S + s + 3) * D + d] = wk * u4.w;
    } else {
        // ---------- orth pair (s,t) dots; 4 t per thread ----------
        const int kk[10] = {0, 0, 0, 0, 1, 1, 1, 2, 2, 3};
        const int ll[10] = {0, 1, 2, 3, 1, 2, 3, 2, 3, 3};
        int p = bx - 800;
        int k = kk[p], l = ll[p];
        int s = tid >> 3;
        int t0 = (tid & 7) * 4;
        float* uk = sm;
        float* ul = sm + 2048;
        float* red = sm + 4096;
        float c0 = 0.f, c1 = 0.f, c2 = 0.f, c3 = 0.f;
        for (int dc = 0; dc < D; dc += 64) {
            for (int i = tid; i < 2048; i += 256) {
                uk[i] = U[((size_t)k * D + dc) * S + i];
                ul[i] = U[((size_t)l * D + dc) * S + i];
            }
            __syncthreads();
#pragma unroll 8
            for (int d = 0; d < 64; d++) {
                float a = uk[d * 32 + s];
                float4 b = *(const float4*)&ul[d * 32 + t0];
                c0 += a * b.x; c1 += a * b.y; c2 += a * b.z; c3 += a * b.w;
            }
            __syncthreads();
        }
        if (k == l) {
            if (s == t0 + 0) c0 -= 1.0f;
            if (s == t0 + 1) c1 -= 1.0f;
            if (s == t0 + 2) c2 -= 1.0f;
            if (s == t0 + 3) c3 -= 1.0f;
        }
        red[tid] = (c0 * c0 + c1 * c1) + (c2 * c2 + c3 * c3);
        __syncthreads();
        for (int off = 128; off > 0; off >>= 1) {
            if (tid < off) red[tid] += red[tid + off];
            __syncthreads();
        }
        if (tid == 0) g_orth[p] = red[0];
    }
}

// ================= MZt = Minv[k] @ Zt rows : conflict-free, 4 rows/warp =================
__global__ void k_MZ(void) {
    __shared__ float Msh[32 * 33];
    __shared__ float zsh[32 * 33];
    int k = blockIdx.y;
    int n0 = blockIdx.x * 32;
    int tid = threadIdx.x;
    int w = tid >> 5;
    int lane = tid & 31;
    {
        float4 v = ((const float4*)(g_Minv + k * S * S))[tid];
        int r = (tid * 4) >> 5;
        int c = (tid * 4) & 31;
        float* dst = &Msh[r * 33 + c];
        dst[0] = v.x; dst[1] = v.y; dst[2] = v.z; dst[3] = v.w;
    }
    {
        int r = tid >> 3, q = tid & 7;
        float4 v = *(const float4*)&g_Zt[((size_t)k * N + n0 + r) * S + q * 4];
        float* dst = &zsh[r * 33 + q * 4];
        dst[0] = v.x; dst[1] = v.y; dst[2] = v.z; dst[3] = v.w;
    }
    __syncthreads();
    float a0 = 0.f, a1 = 0.f, a2 = 0.f, a3 = 0.f;
    const float* z0 = &zsh[(w * 4 + 0) * 33];
    const float* z1 = &zsh[(w * 4 + 1) * 33];
    const float* z2 = &zsh[(w * 4 + 2) * 33];
    const float* z3 = &zsh[(w * 4 + 3) * 33];
#pragma unroll
    for (int t = 0; t < 32; t++) {
        float mv = Msh[t * 33 + lane];
        a0 += mv * z0[t];
        a1 += mv * z1[t];
        a2 += mv * z2[t];
        a3 += mv * z3[t];
    }
    size_t base = ((size_t)k * N + n0 + w * 4) * S + lane;
    g_MZt[base] = a0;
    g_MZt[base + S] = a1;
    g_MZt[base + 2 * S] = a2;
    g_MZt[base + 3 * S] = a3;
}

// ================= sparse attention: 4 lanes/row, 8-row chunks, 1-deep value pipeline =================
// lane = (rr = lane>>2 : row 0..7, f2 = lane&3 : 8-float segment).
// Iteration i computes on v-registers loaded in iteration i-1; next chunk's v-rows
// and the index two chunks ahead load in the shadow of the compute.
__global__ void __launch_bounds__(256) k_attn(void) {
    int w = threadIdx.x >> 5;
    int lane = threadIdx.x & 31;
    int gwarp = blockIdx.x * 8 + w;
    int k = gwarp >> 12;
    int n = gwarp & (N - 1);
    const float* __restrict__ MZ = g_MZt + (size_t)k * N * S;
    const int* __restrict__ cols = g_col + (size_t)n * MAXDEG;
    int dn = g_deg[n];
    int f2 = lane & 3;
    int rr = lane >> 2;
    const float LOG2E = 1.4426950408889634f;
    const float* qp = &g_Zt[((size_t)k * N + n) * S + f2 * 8];
    float4 qa = *(const float4*)&qp[0];
    float4 qb = *(const float4*)&qp[4];
    qa.x *= LOG2E; qa.y *= LOG2E; qa.z *= LOG2E; qa.w *= LOG2E;
    qb.x *= LOG2E; qb.y *= LOG2E; qb.z *= LOG2E; qb.w *= LOG2E;

    float4 aa = make_float4(0.f, 0.f, 0.f, 0.f);
    float4 ab = make_float4(0.f, 0.f, 0.f, 0.f);
    float l = 0.f;

    // prologue: chunk0 values resident, chunk1 index resident
    int jc = (rr < dn) ? cols[rr] : 0;
    int jn = (8 + rr < dn) ? cols[8 + rr] : 0;
    const float* vp = &MZ[(size_t)jc * S + f2 * 8];
    float4 va = *(const float4*)&vp[0];
    float4 vb = *(const float4*)&vp[4];

    for (int c0 = 0; c0 < dn; c0 += 8) {
        // prefetch next chunk's values (index known) + index two chunks ahead
        const float* vpn = &MZ[(size_t)jn * S + f2 * 8];
        float4 van = *(const float4*)&vpn[0];
        float4 vbn = *(const float4*)&vpn[4];
        int nr = c0 + 16 + rr;
        int j2 = (nr < dn) ? cols[nr] : 0;

        // compute on current (register-resident) values
        float p = qa.x * va.x + qa.y * va.y + qa.z * va.z + qa.w * va.w
                + qb.x * vb.x + qb.y * vb.y + qb.z * vb.z + qb.w * vb.w;
        p += __shfl_xor_sync(0xffffffffu, p, 1);
        p += __shfl_xor_sync(0xffffffffu, p, 2);
        p = (c0 + rr < dn) ? p : -1e30f;
        float e = exp2f(p);
        l += e;
        aa.x += e * va.x; aa.y += e * va.y; aa.z += e * va.z; aa.w += e * va.w;
        ab.x += e * vb.x; ab.y += e * vb.y; ab.z += e * vb.z; ab.w += e * vb.w;

        va = van; vb = vbn; jn = j2;
    }

    // fold across the 8 rr-groups (xor 4, 8, 16)
#pragma unroll
    for (int off = 4; off <= 16; off <<= 1) {
        aa.x += __shfl_xor_sync(0xffffffffu, aa.x, off);
        aa.y += __shfl_xor_sync(0xffffffffu, aa.y, off);
        aa.z += __shfl_xor_sync(0xffffffffu, aa.z, off);
        aa.w += __shfl_xor_sync(0xffffffffu, aa.w, off);
        ab.x += __shfl_xor_sync(0xffffffffu, ab.x, off);
        ab.y += __shfl_xor_sync(0xffffffffu, ab.y, off);
        ab.z += __shfl_xor_sync(0xffffffffu, ab.z, off);
        ab.w += __shfl_xor_sync(0xffffffffu, ab.w, off);
        l    += __shfl_xor_sync(0xffffffffu, l, off);
    }
    if (rr == 0) {
        float inv = 1.0f / l;
        float* dst = &g_O[(size_t)n * (K * S) + k * S + f2 * 8];
        *(float4*)&dst[0] = make_float4(aa.x * inv, aa.y * inv, aa.z * inv, aa.w * inv);
        *(float4*)&dst[4] = make_float4(ab.x * inv, ab.y * inv, ab.z * inv, ab.w * inv);
    }
}

// ================= O2 = (I - lam*L) @ O_cat =================
__global__ void k_lapO(const float* __restrict__ lambda_lap) {
    int n = blockIdx.x * 8 + (threadIdx.x >> 5);
    int lane = threadIdx.x & 31;
    const float4* O = (const float4*)g_O;
    const int* cols = g_col + (size_t)n * MAXDEG;
    int dn = g_deg[n];
    float4 o = O[(size_t)n * 32 + lane];
    float4 s = make_float4(0.f, 0.f, 0.f, 0.f);
    int c = 0;
    for (; c + 4 <= dn; c += 4) {
        float4 v0 = O[(size_t)cols[c] * 32 + lane];
        float4 v1 = O[(size_t)cols[c + 1] * 32 + lane];
        float4 v2 = O[(size_t)cols[c + 2] * 32 + lane];
        float4 v3 = O[(size_t)cols[c + 3] * 32 + lane];
        s.x += (v0.x + v1.x) + (v2.x + v3.x);
        s.y += (v0.y + v1.y) + (v2.y + v3.y);
        s.z += (v0.z + v1.z) + (v2.z + v3.z);
        s.w += (v0.w + v1.w) + (v2.w + v3.w);
    }
    for (; c < dn; c++) {
        float4 v = O[(size_t)cols[c] * 32 + lane];
        s.x += v.x; s.y += v.y; s.z += v.z; s.w += v.w;
    }
    float lam = lambda_lap[0];
    float fd = (float)dn;
    float4 r;
    r.x = o.x - lam * (fd * o.x - s.x);
    r.y = o.y - lam * (fd * o.y - s.y);
    r.z = o.z - lam * (fd * o.z - s.z);
    r.w = o.w - lam * (fd * o.w - s.w);
    ((float4*)g_O2)[(size_t)n * 32 + lane] = r;
}

// ================= H_out = softthresh(hops0 + ETA * O2 @ Wc) =================
__global__ void k_HoutG(const float* __restrict__ hops,
                        const float* __restrict__ threshold,
                        float* __restrict__ out) {
    __shared__ float as[32][33];
    __shared__ float ws[32][33];
    int n0 = blockIdx.x * 32, d0 = blockIdx.y * 32;
    int lane = threadIdx.x & 31;
    int row = threadIdx.x >> 5;
    float acc[4] = {0.f, 0.f, 0.f, 0.f};
    for (int cc = 0; cc < K * S; cc += 32) {
#pragma unroll
        for (int i = 0; i < 4; i++) {
            int r = row + i * 8;
            as[r][lane] = g_O2[(size_t)(n0 + r) * (K * S) + cc + lane];
            ws[r][lane] = g_Wc[(size_t)(cc + r) * D + d0 + lane];
        }
        __syncthreads();
#pragma unroll
        for (int dd = 0; dd < 32; dd++) {
            float wv = ws[dd][lane];
#pragma unroll
            for (int i = 0; i < 4; i++) acc[i] += as[row * 4 + i][dd] * wv;
        }
        __syncthreads();
    }
    float th = threshold[d0 + lane];
#pragma unroll
    for (int i = 0; i < 4; i++) {
        int n = n0 + row * 4 + i;
        float hh = hops[(size_t)n * D + d0 + lane] + ETA * acc[i];
        float ab = fabsf(hh) - th;
        out[(size_t)n * D + d0 + lane] = (ab > 0.f) ? copysignf(ab, hh) : 0.f;
    }
}

// ================= lap_smooth partials (symmetric half) + fused final =================
__global__ void k_lapF(const float* __restrict__ Hout, const float* __restrict__ hw,
                       float* __restrict__ out, int out_size) {
    __shared__ int hd[4];
    if (threadIdx.x < 4) {
        int nn = blockIdx.x * 4 + threadIdx.x;
        const int* cc = g_col + (size_t)nn * MAXDEG;
        int lo = 0, hi = g_deg[nn];
        while (lo < hi) {
            int mid = (lo + hi) >> 1;
            if (cc[mid] < nn) lo = mid + 1; else hi = mid;
        }
        hd[threadIdx.x] = lo;
    }
    __syncthreads();
    int g = threadIdx.x >> 6;
    int n = blockIdx.x * 4 + g;
    int t = threadIdx.x & 63;
    const float4* H = (const float4*)Hout;
    const int* cols = g_col + (size_t)n * MAXDEG;
    int dn = g_deg[n];
    int hn = hd[g];
    float4 h = H[(size_t)n * 64 + t];
    float4 vs = make_float4(0.f, 0.f, 0.f, 0.f);
    int c = 0;
    for (; c + 4 <= hn; c += 4) {
        float4 v0 = H[(size_t)cols[c] * 64 + t];
        float4 v1 = H[(size_t)cols[c + 1] * 64 + t];
        float4 v2 = H[(size_t)cols[c + 2] * 64 + t];
        float4 v3 = H[(size_t)cols[c + 3] * 64 + t];
        vs.x += (v0.x + v1.x) + (v2.x + v3.x);
        vs.y += (v0.y + v1.y) + (v2.y + v3.y);
        vs.z += (v0.z + v1.z) + (v2.z + v3.z);
        vs.w += (v0.w + v1.w) + (v2.w + v3.w);
    }
    for (; c < hn; c++) {
        float4 v = H[(size_t)cols[c] * 64 + t];
        vs.x += v.x; vs.y += v.y; vs.z += v.z; vs.w += v.w;
    }
    float fd = (float)dn - 1.0f;
    float dot = fd * (h.x * h.x + h.y * h.y + h.z * h.z + h.w * h.w)
              - 2.0f * (h.x * vs.x + h.y * vs.y + h.z * vs.z + h.w * vs.w);
    dot = warpSum(dot);
    __shared__ float sred[8];
    if ((threadIdx.x & 31) == 0) sred[threadIdx.x >> 5] = dot;
    __syncthreads();
    if (threadIdx.x < 4)
        g_partials[blockIdx.x * 4 + threadIdx.x] =
            sred[threadIdx.x * 2] + sred[threadIdx.x * 2 + 1];

    __threadfence();
    __shared__ int isLast;
    if (threadIdx.x == 0) {
        int v = atomicAdd(&g_ctr, 1);
        isLast = (v == (int)gridDim.x - 1) ? 1 : 0;
        if (isLast) atomicExch(&g_ctr, 0);
    }
    __syncthreads();
    if (!isLast) return;
    __threadfence();

    float v = 0.f;
    for (int i = threadIdx.x; i < N; i += 256) v += g_partials[i];
    __shared__ float red2[256];
    red2[threadIdx.x] = v;
    __syncthreads();
    for (int off = 128; off > 0; off >>= 1) {
        if (threadIdx.x < off) red2[threadIdx.x] += red2[threadIdx.x + off];
        __syncthreads();
    }
    if (threadIdx.x == 0) {
        float orth = 0.f;
        for (int p = 0; p < 10; p++) orth += g_orth[p];
        float m = fmaxf(fmaxf(hw[0], hw[1]), fmaxf(hw[2], hw[3]));
        float e0 = expf(hw[0] - m), e1 = expf(hw[1] - m);
        float e2 = expf(hw[2] - m), e3 = expf(hw[3] - m);
        float s = e0 + e1 + e2 + e3;
        int base = N * D;
        if (base < out_size) out[base] = orth;
        if (base + 1 < out_size) out[base + 1] = red2[0];
        if (base + 2 < out_size) out[base + 2] = e0 / s;
        if (base + 3 < out_size) out[base + 3] = e1 / s;
        if (base + 4 < out_size) out[base + 4] = e2 / s;
        if (base + 5 < out_size) out[base + 5] = e3 / s;
    }
}

// ---------------- launch ----------------
extern "C" void kernel_launch(void* const* d_in, const int* in_sizes, int n_in,
                              void* d_out, int out_size) {
    const float* hops      = (const float*)d_in[0];
    const float* adj       = (const float*)d_in[1];
    const float* U         = (const float*)d_in[3];
    const float* hw        = (const float*)d_in[4];
    const float* threshold = (const float*)d_in[5];
    const float* lam       = (const float*)d_in[6];
    float* out = (float*)d_out;

    k_mega1<<<810, 256>>>(hops, adj, U, hw);
    {
        dim3 g(N / 32, K);
        k_MZ<<<g, 256>>>();
    }
    k_attn<<<(K * N) / 8, 256>>>();
    k_lapO<<<N / 8, 256>>>(lam);
    {
        dim3 g(N / 32, D / 32);
        k_HoutG<<<g, 256>>>(hops, threshold, out);
    }
    k_lapF<<<N / 4, 256>>>(out, hw, out, out_size);
}

// round 13
// speedup vs baseline: 1.0587x; 1.0587x over previous
#include <cuda_runtime.h>
#include <math.h>

#define K 4
#define N 4096
#define D 256
#define S 32
#define MAXDEG 512
#define ETA 0.5f
#define COEFF 0.03125f   // S/(N*EPS^2)

// ---------------- scratch ----------------
__device__ float g_Zt[K * N * S];        // [k][n][s]
__device__ float g_MZt[K * N * S];       // [k][n][s]
__device__ float g_Minv[K * S * S];
__device__ float g_O[(size_t)N * (K * S)];   // O_cat: [n][k*S+s]
__device__ float g_O2[(size_t)N * (K * S)];  // (I - lam*L) @ O_cat
__device__ float g_Wc[K * S * D];        // w_k * U[k]^T : [k*S+s][d]
__device__ float g_gramP[K * 32 * S * S];
__device__ int   g_col[(size_t)N * MAXDEG];
__device__ int   g_deg[N];
__device__ float g_partials[N];
__device__ float g_orth[10];
__device__ int   g_ctr;       // zero-init; self-resetting
__device__ int   g_ctrK[K];   // zero-init; self-resetting

__device__ __forceinline__ float warpSum(float v) {
    v += __shfl_xor_sync(0xffffffffu, v, 16);
    v += __shfl_xor_sync(0xffffffffu, v, 8);
    v += __shfl_xor_sync(0xffffffffu, v, 4);
    v += __shfl_xor_sync(0xffffffffu, v, 2);
    v += __shfl_xor_sync(0xffffffffu, v, 1);
    return v;
}

// ================= mega kernel 1: Z (0..255) | CSR (256..767) | Wc (768..799) | orth (800..809) =================
__global__ void __launch_bounds__(256) k_mega1(const float* __restrict__ hops,
                                               const float* __restrict__ adj,
                                               const float* __restrict__ U,
                                               const float* __restrict__ hw) {
    __shared__ float sm[6528];
    int bx = blockIdx.x;
    int tid = threadIdx.x;

    if (bx < 256) {
        // ---------- Z = hops[k] @ U[k] : 64n x 32s tile, double-buffered ----------
        int k = bx >> 6;
        int n0 = (bx & 63) * 64;
        float* hsT0 = sm;            // 32*66
        float* hsT1 = sm + 2112;
        float* us0  = sm + 4224;     // 32*36
        float* us1  = sm + 5376;
        int ny = tid >> 3;
        int sx = (tid & 7) * 4;
        int rowq = tid >> 3;
        int q = tid & 7;
        const float* Hb = hops + ((size_t)k * N + n0) * D;
        const float* Ub = U + (size_t)k * D * S;

        float4 h0, h1, u0;
        h0 = *(const float4*)&Hb[(size_t)rowq * D + q * 4];
        h1 = *(const float4*)&Hb[(size_t)(rowq + 32) * D + q * 4];
        u0 = *(const float4*)&Ub[(size_t)rowq * S + q * 4];
        {
            float* hb = hsT0;
            hb[(q * 4 + 0) * 66 + rowq] = h0.x;
            hb[(q * 4 + 1) * 66 + rowq] = h0.y;
            hb[(q * 4 + 2) * 66 + rowq] = h0.z;
            hb[(q * 4 + 3) * 66 + rowq] = h0.w;
            hb[(q * 4 + 0) * 66 + rowq + 32] = h1.x;
            hb[(q * 4 + 1) * 66 + rowq + 32] = h1.y;
            hb[(q * 4 + 2) * 66 + rowq + 32] = h1.z;
            hb[(q * 4 + 3) * 66 + rowq + 32] = h1.w;
            *(float4*)&us0[rowq * 36 + q * 4] = u0;
        }
        __syncthreads();

        float a0x = 0.f, a0y = 0.f, a0z = 0.f, a0w = 0.f;
        float a1x = 0.f, a1y = 0.f, a1z = 0.f, a1w = 0.f;

        for (int ch = 0; ch < 8; ch++) {
            const float* hb = (ch & 1) ? hsT1 : hsT0;
            const float* ub = (ch & 1) ? us1 : us0;
            if (ch < 7) {
                int dc = (ch + 1) * 32;
                h0 = *(const float4*)&Hb[(size_t)rowq * D + dc + q * 4];
                h1 = *(const float4*)&Hb[(size_t)(rowq + 32) * D + dc + q * 4];
                u0 = *(const float4*)&Ub[(size_t)(dc + rowq) * S + q * 4];
            }
#pragma unroll
            for (int d = 0; d < 32; d++) {
                float2 h = *(const float2*)&hb[d * 66 + ny * 2];
                float4 u = *(const float4*)&ub[d * 36 + sx];
                a0x += h.x * u.x; a0y += h.x * u.y; a0z += h.x * u.z; a0w += h.x * u.w;
                a1x += h.y * u.x; a1y += h.y * u.y; a1z += h.y * u.z; a1w += h.y * u.w;
            }
            if (ch < 7) {
                float* hb2 = (ch & 1) ? hsT0 : hsT1;
                float* ub2 = (ch & 1) ? us0 : us1;
                hb2[(q * 4 + 0) * 66 + rowq] = h0.x;
                hb2[(q * 4 + 1) * 66 + rowq] = h0.y;
                hb2[(q * 4 + 2) * 66 + rowq] = h0.z;
                hb2[(q * 4 + 3) * 66 + rowq] = h0.w;
                hb2[(q * 4 + 0) * 66 + rowq + 32] = h1.x;
                hb2[(q * 4 + 1) * 66 + rowq + 32] = h1.y;
                hb2[(q * 4 + 2) * 66 + rowq + 32] = h1.z;
                hb2[(q * 4 + 3) * 66 + rowq + 32] = h1.w;
                *(float4*)&ub2[rowq * 36 + q * 4] = u0;
            }
            __syncthreads();
        }
        size_t base = ((size_t)k * N + n0 + ny * 2) * S + sx;
        *(float4*)&g_Zt[base] = make_float4(a0x, a0y, a0z, a0w);
        *(float4*)&g_Zt[base + S] = make_float4(a1x, a1y, a1z, a1w);
    } else if (bx < 768) {
        // ---------- CSR build (warp per row, float4 + 4 ballots per 128 cols) ----------
        int n = (bx - 256) * 8 + (tid >> 5);
        int lane = tid & 31;
        const float4* row = (const float4*)(adj + (size_t)n * N);
        int* dst = g_col + (size_t)n * MAXDEG;
        unsigned lm = (1u << lane) - 1u;
        int cnt = 0;
        for (int base = 0; base < N / 4; base += 32) {
            float4 a = row[base + lane];
            unsigned m0 = __ballot_sync(0xffffffffu, a.x != 0.0f);
            unsigned m1 = __ballot_sync(0xffffffffu, a.y != 0.0f);
            unsigned m2 = __ballot_sync(0xffffffffu, a.z != 0.0f);
            unsigned m3 = __ballot_sync(0xffffffffu, a.w != 0.0f);
            int pre = cnt + __popc(m0 & lm) + __popc(m1 & lm)
                          + __popc(m2 & lm) + __popc(m3 & lm);
            int j0 = (base + lane) * 4;
            if (a.x != 0.0f) dst[pre] = j0;
            int o1 = pre + ((m0 >> lane) & 1);
            if (a.y != 0.0f) dst[o1] = j0 + 1;
            int o2 = o1 + ((m1 >> lane) & 1);
            if (a.z != 0.0f) dst[o2] = j0 + 2;
            int o3 = o2 + ((m2 >> lane) & 1);
            if (a.w != 0.0f) dst[o3] = j0 + 3;
            cnt += __popc(m0) + __popc(m1) + __popc(m2) + __popc(m3);
        }
        if (lane == 0) g_deg[n] = min(cnt, MAXDEG);
    } else if (bx < 800) {
        // ---------- Wc[k*S+s][d] = w_k * U[k][d][s] ----------
        float m = fmaxf(fmaxf(hw[0], hw[1]), fmaxf(hw[2], hw[3]));
        float e0 = expf(hw[0] - m), e1 = expf(hw[1] - m);
        float e2 = expf(hw[2] - m), e3 = expf(hw[3] - m);
        float sum = e0 + e1 + e2 + e3;
        int base = ((bx - 768) * 256 + tid) * 4;
        float4 u4 = *(const float4*)&U[base];
        int k = base / (D * S);
        int rem = base % (D * S);
        int d = rem / S;
        int s = rem % S;
        float wk = (k == 0 ? e0 : k == 1 ? e1 : k == 2 ? e2 : e3) / sum;
        g_Wc[(k * S + s + 0) * D + d] = wk * u4.x;
        g_Wc[(k * S + s + 1) * D + d] = wk * u4.y;
        g_Wc[(k * S + s + 2) * D + d] = wk * u4.z;
        g_Wc[(k * S + s + 3) * D + d] = wk * u4.w;
    } else {
        // ---------- orth pair (s,t) dots; 4 t per thread ----------
        const int kk[10] = {0, 0, 0, 0, 1, 1, 1, 2, 2, 3};
        const int ll[10] = {0, 1, 2, 3, 1, 2, 3, 2, 3, 3};
        int p = bx - 800;
        int k = kk[p], l = ll[p];
        int s = tid >> 3;
        int t0 = (tid & 7) * 4;
        float* uk = sm;
        float* ul = sm + 2048;
        float* red = sm + 4096;
        float c0 = 0.f, c1 = 0.f, c2 = 0.f, c3 = 0.f;
        for (int dc = 0; dc < D; dc += 64) {
            for (int i = tid; i < 2048; i += 256) {
                uk[i] = U[((size_t)k * D + dc) * S + i];
                ul[i] = U[((size_t)l * D + dc) * S + i];
            }
            __syncthreads();
#pragma unroll 8
            for (int d = 0; d < 64; d++) {
                float a = uk[d * 32 + s];
                float4 b = *(const float4*)&ul[d * 32 + t0];
                c0 += a * b.x; c1 += a * b.y; c2 += a * b.z; c3 += a * b.w;
            }
            __syncthreads();
        }
        if (k == l) {
            if (s == t0 + 0) c0 -= 1.0f;
            if (s == t0 + 1) c1 -= 1.0f;
            if (s == t0 + 2) c2 -= 1.0f;
            if (s == t0 + 3) c3 -= 1.0f;
        }
        red[tid] = (c0 * c0 + c1 * c1) + (c2 * c2 + c3 * c3);
        __syncthreads();
        for (int off = 128; off > 0; off >>= 1) {
            if (tid < off) red[tid] += red[tid + off];
            __syncthreads();
        }
        if (tid == 0) g_orth[p] = red[0];
    }
}

// ================= gram partials + last-block-per-k inversion =================
__global__ void __launch_bounds__(1024) k_gram(void) {
    __shared__ float sm[4224];
    int tid = threadIdx.x;
    int k = blockIdx.x >> 5;
    int chunk = blockIdx.x & 31;
    float* zs = sm;
    const float4* Z4 = (const float4*)(g_Zt + ((size_t)k * N + chunk * 128) * S);
    ((float4*)zs)[tid] = Z4[tid];
    __syncthreads();
    int s = tid >> 5, t = tid & 31;
    float g0 = 0.f, g1 = 0.f, g2 = 0.f, g3 = 0.f;
#pragma unroll 8
    for (int n = 0; n < 128; n += 4) {
        g0 += zs[(n + 0) * 32 + s] * zs[(n + 0) * 32 + t];
        g1 += zs[(n + 1) * 32 + s] * zs[(n + 1) * 32 + t];
        g2 += zs[(n + 2) * 32 + s] * zs[(n + 2) * 32 + t];
        g3 += zs[(n + 3) * 32 + s] * zs[(n + 3) * 32 + t];
    }
    g_gramP[(((size_t)k * 32 + chunk) * S + s) * S + t] = (g0 + g1) + (g2 + g3);
    __threadfence();
    __shared__ int isLast;
    if (tid == 0) {
        int v = atomicAdd(&g_ctrK[k], 1);
        isLast = (v == 31);
        if (v == 31) atomicExch(&g_ctrK[k], 0);
    }
    __syncthreads();
    if (!isLast) return;
    __threadfence();
    float g = 0.f;
    for (int c = 0; c < 32; c++)
        g += g_gramP[(((size_t)k * 32 + c) * S + s) * S + t];
    float (*aug)[66] = (float(*)[66])sm;
    __syncthreads();
    aug[s][t] = (s == t ? 1.0f : 0.0f) + COEFF * g;
    aug[s][32 + t] = (s == t ? 1.0f : 0.0f);
    __syncthreads();
    int r0 = tid >> 6, c0 = tid & 63;
    int tid2 = tid + 1024;
    int r1 = tid2 >> 6, c1 = tid2 & 63;
    for (int p = 0; p < 32; p++) {
        float inv = 1.0f / aug[p][p];
        float f0 = aug[r0][p], pr0 = aug[p][c0];
        float f1 = aug[r1][p], pr1 = aug[p][c1];
        __syncthreads();
        if (r0 == p) aug[p][c0] = pr0 * inv;
        else         aug[r0][c0] -= f0 * inv * pr0;
        if (r1 == p) aug[p][c1] = pr1 * inv;
        else         aug[r1][c1] -= f1 * inv * pr1;
        __syncthreads();
    }
    g_Minv[k * S * S + s * S + t] = aug[s][32 + t];
}

// ================= MZt = Minv[k] @ Zt rows : conflict-free, 4 rows/warp =================
__global__ void k_MZ(void) {
    __shared__ float Msh[32 * 33];
    __shared__ float zsh[32 * 33];
    int k = blockIdx.y;
    int n0 = blockIdx.x * 32;
    int tid = threadIdx.x;
    int w = tid >> 5;
    int lane = tid & 31;
    {
        float4 v = ((const float4*)(g_Minv + k * S * S))[tid];
        int r = (tid * 4) >> 5;
        int c = (tid * 4) & 31;
        float* dst = &Msh[r * 33 + c];
        dst[0] = v.x; dst[1] = v.y; dst[2] = v.z; dst[3] = v.w;
    }
    {
        int r = tid >> 3, q = tid & 7;
        float4 v = *(const float4*)&g_Zt[((size_t)k * N + n0 + r) * S + q * 4];
        float* dst = &zsh[r * 33 + q * 4];
        dst[0] = v.x; dst[1] = v.y; dst[2] = v.z; dst[3] = v.w;
    }
    __syncthreads();
    float a0 = 0.f, a1 = 0.f, a2 = 0.f, a3 = 0.f;
    const float* z0 = &zsh[(w * 4 + 0) * 33];
    const float* z1 = &zsh[(w * 4 + 1) * 33];
    const float* z2 = &zsh[(w * 4 + 2) * 33];
    const float* z3 = &zsh[(w * 4 + 3) * 33];
#pragma unroll
    for (int t = 0; t < 32; t++) {
        float mv = Msh[t * 33 + lane];
        a0 += mv * z0[t];
        a1 += mv * z1[t];
        a2 += mv * z2[t];
        a3 += mv * z3[t];
    }
    size_t base = ((size_t)k * N + n0 + w * 4) * S + lane;
    g_MZt[base] = a0;
    g_MZt[base + S] = a1;
    g_MZt[base + 2 * S] = a2;
    g_MZt[base + 3 * S] = a3;
}

// ================= sparse attention: 4 lanes/row, pipelined column prefetch =================
__global__ void __launch_bounds__(256) k_attn(void) {
    int w = threadIdx.x >> 5;
    int lane = threadIdx.x & 31;
    int gwarp = blockIdx.x * 8 + w;
    int k = gwarp >> 12;
    int n = gwarp & (N - 1);
    const float* __restrict__ MZ = g_MZt + (size_t)k * N * S;
    const int* __restrict__ cols = g_col + (size_t)n * MAXDEG;
    int dn = g_deg[n];
    int f2 = lane & 3;
    int rr = lane >> 2;
    const float LOG2E = 1.4426950408889634f;
    const float* qp = &g_Zt[((size_t)k * N + n) * S + f2 * 8];
    float4 qa = *(const float4*)&qp[0];
    float4 qb = *(const float4*)&qp[4];
    qa.x *= LOG2E; qa.y *= LOG2E; qa.z *= LOG2E; qa.w *= LOG2E;
    qb.x *= LOG2E; qb.y *= LOG2E; qb.z *= LOG2E; qb.w *= LOG2E;

    float4 aa = make_float4(0.f, 0.f, 0.f, 0.f);
    float4 ab = make_float4(0.f, 0.f, 0.f, 0.f);
    float l = 0.f;

    // prologue: indices for chunk 0
    int j0 = (rr < dn) ? cols[rr] : 0;
    int j1 = (8 + rr < dn) ? cols[8 + rr] : 0;

    for (int c0 = 0; c0 < dn; c0 += 16) {
        const float* vp0 = &MZ[(size_t)j0 * S + f2 * 8];
        const float* vp1 = &MZ[(size_t)j1 * S + f2 * 8];
        float4 va0 = *(const float4*)&vp0[0];
        float4 vb0 = *(const float4*)&vp0[4];
        float4 va1 = *(const float4*)&vp1[0];
        float4 vb1 = *(const float4*)&vp1[4];
        int nr0 = c0 + 16 + rr, nr1 = c0 + 24 + rr;
        int jn0 = (nr0 < dn) ? cols[nr0] : 0;
        int jn1 = (nr1 < dn) ? cols[nr1] : 0;

        bool in0 = (c0 + rr < dn);
        bool in1 = (c0 + 8 + rr < dn);

        float p0 = qa.x * va0.x + qa.y * va0.y + qa.z * va0.z + qa.w * va0.w
                 + qb.x * vb0.x + qb.y * vb0.y + qb.z * vb0.z + qb.w * vb0.w;
        float p1 = qa.x * va1.x + qa.y * va1.y + qa.z * va1.z + qa.w * va1.w
                 + qb.x * vb1.x + qb.y * vb1.y + qb.z * vb1.z + qb.w * vb1.w;
        p0 += __shfl_xor_sync(0xffffffffu, p0, 1);
        p1 += __shfl_xor_sync(0xffffffffu, p1, 1);
        p0 += __shfl_xor_sync(0xffffffffu, p0, 2);
        p1 += __shfl_xor_sync(0xffffffffu, p1, 2);
        p0 = in0 ? p0 : -1e30f;
        p1 = in1 ? p1 : -1e30f;
        float e0 = exp2f(p0);
        float e1 = exp2f(p1);
        l += e0 + e1;
        aa.x += e0 * va0.x; aa.y += e0 * va0.y; aa.z += e0 * va0.z; aa.w += e0 * va0.w;
        ab.x += e0 * vb0.x; ab.y += e0 * vb0.y; ab.z += e0 * vb0.z; ab.w += e0 * vb0.w;
        aa.x += e1 * va1.x; aa.y += e1 * va1.y; aa.z += e1 * va1.z; aa.w += e1 * va1.w;
        ab.x += e1 * vb1.x; ab.y += e1 * vb1.y; ab.z += e1 * vb1.z; ab.w += e1 * vb1.w;

        j0 = jn0; j1 = jn1;
    }

#pragma unroll
    for (int off = 4; off <= 16; off <<= 1) {
        aa.x += __shfl_xor_sync(0xffffffffu, aa.x, off);
        aa.y += __shfl_xor_sync(0xffffffffu, aa.y, off);
        aa.z += __shfl_xor_sync(0xffffffffu, aa.z, off);
        aa.w += __shfl_xor_sync(0xffffffffu, aa.w, off);
        ab.x += __shfl_xor_sync(0xffffffffu, ab.x, off);
        ab.y += __shfl_xor_sync(0xffffffffu, ab.y, off);
        ab.z += __shfl_xor_sync(0xffffffffu, ab.z, off);
        ab.w += __shfl_xor_sync(0xffffffffu, ab.w, off);
        l    += __shfl_xor_sync(0xffffffffu, l, off);
    }
    if (rr == 0) {
        float inv = 1.0f / l;
        float* dst = &g_O[(size_t)n * (K * S) + k * S + f2 * 8];
        *(float4*)&dst[0] = make_float4(aa.x * inv, aa.y * inv, aa.z * inv, aa.w * inv);
        *(float4*)&dst[4] = make_float4(ab.x * inv, ab.y * inv, ab.z * inv, ab.w * inv);
    }
}

// ================= O2 = (I - lam*L) @ O_cat : 8-wide MLP gather =================
__global__ void k_lapO(const float* __restrict__ lambda_lap) {
    int n = blockIdx.x * 8 + (threadIdx.x >> 5);
    int lane = threadIdx.x & 31;
    const float4* O = (const float4*)g_O;
    const int* cols = g_col + (size_t)n * MAXDEG;
    int dn = g_deg[n];
    float4 o = O[(size_t)n * 32 + lane];
    float4 s = make_float4(0.f, 0.f, 0.f, 0.f);
    int c = 0;
    for (; c + 8 <= dn; c += 8) {
        float4 v0 = O[(size_t)cols[c] * 32 + lane];
        float4 v1 = O[(size_t)cols[c + 1] * 32 + lane];
        float4 v2 = O[(size_t)cols[c + 2] * 32 + lane];
        float4 v3 = O[(size_t)cols[c + 3] * 32 + lane];
        float4 v4 = O[(size_t)cols[c + 4] * 32 + lane];
        float4 v5 = O[(size_t)cols[c + 5] * 32 + lane];
        float4 v6 = O[(size_t)cols[c + 6] * 32 + lane];
        float4 v7 = O[(size_t)cols[c + 7] * 32 + lane];
        s.x += ((v0.x + v1.x) + (v2.x + v3.x)) + ((v4.x + v5.x) + (v6.x + v7.x));
        s.y += ((v0.y + v1.y) + (v2.y + v3.y)) + ((v4.y + v5.y) + (v6.y + v7.y));
        s.z += ((v0.z + v1.z) + (v2.z + v3.z)) + ((v4.z + v5.z) + (v6.z + v7.z));
        s.w += ((v0.w + v1.w) + (v2.w + v3.w)) + ((v4.w + v5.w) + (v6.w + v7.w));
    }
    for (; c < dn; c++) {
        float4 v = O[(size_t)cols[c] * 32 + lane];
        s.x += v.x; s.y += v.y; s.z += v.z; s.w += v.w;
    }
    float lam = lambda_lap[0];
    float fd = (float)dn;
    float4 r;
    r.x = o.x - lam * (fd * o.x - s.x);
    r.y = o.y - lam * (fd * o.y - s.y);
    r.z = o.z - lam * (fd * o.z - s.z);
    r.w = o.w - lam * (fd * o.w - s.w);
    ((float4*)g_O2)[(size_t)n * 32 + lane] = r;
}

// ================= H_out = softthresh(hops0 + ETA * O2 @ Wc) =================
__global__ void k_HoutG(const float* __restrict__ hops,
                        const float* __restrict__ threshold,
                        float* __restrict__ out) {
    __shared__ float as[32][33];
    __shared__ float ws[32][33];
    int n0 = blockIdx.x * 32, d0 = blockIdx.y * 32;
    int lane = threadIdx.x & 31;
    int row = threadIdx.x >> 5;
    float acc[4] = {0.f, 0.f, 0.f, 0.f};
    for (int cc = 0; cc < K * S; cc += 32) {
#pragma unroll
        for (int i = 0; i < 4; i++) {
            int r = row + i * 8;
            as[r][lane] = g_O2[(size_t)(n0 + r) * (K * S) + cc + lane];
            ws[r][lane] = g_Wc[(size_t)(cc + r) * D + d0 + lane];
        }
        __syncthreads();
#pragma unroll
        for (int dd = 0; dd < 32; dd++) {
            float wv = ws[dd][lane];
#pragma unroll
            for (int i = 0; i < 4; i++) acc[i] += as[row * 4 + i][dd] * wv;
        }
        __syncthreads();
    }
    float th = threshold[d0 + lane];
#pragma unroll
    for (int i = 0; i < 4; i++) {
        int n = n0 + row * 4 + i;
        float hh = hops[(size_t)n * D + d0 + lane] + ETA * acc[i];
        float ab = fabsf(hh) - th;
        out[(size_t)n * D + d0 + lane] = (ab > 0.f) ? copysignf(ab, hh) : 0.f;
    }
}

// ================= lap_smooth partials (symmetric half, 8-wide MLP) + fused final =================
__global__ void k_lapF(const float* __restrict__ Hout, const float* __restrict__ hw,
                       float* __restrict__ out, int out_size) {
    __shared__ int hd[4];
    if (threadIdx.x < 4) {
        int nn = blockIdx.x * 4 + threadIdx.x;
        const int* cc = g_col + (size_t)nn * MAXDEG;
        int lo = 0, hi = g_deg[nn];
        while (lo < hi) {
            int mid = (lo + hi) >> 1;
            if (cc[mid] < nn) lo = mid + 1; else hi = mid;
        }
        hd[threadIdx.x] = lo;
    }
    __syncthreads();
    int g = threadIdx.x >> 6;
    int n = blockIdx.x * 4 + g;
    int t = threadIdx.x & 63;
    const float4* H = (const float4*)Hout;
    const int* cols = g_col + (size_t)n * MAXDEG;
    int dn = g_deg[n];
    int hn = hd[g];
    float4 h = H[(size_t)n * 64 + t];
    float4 vs = make_float4(0.f, 0.f, 0.f, 0.f);
    int c = 0;
    for (; c + 8 <= hn; c += 8) {
        float4 v0 = H[(size_t)cols[c] * 64 + t];
        float4 v1 = H[(size_t)cols[c + 1] * 64 + t];
        float4 v2 = H[(size_t)cols[c + 2] * 64 + t];
        float4 v3 = H[(size_t)cols[c + 3] * 64 + t];
        float4 v4 = H[(size_t)cols[c + 4] * 64 + t];
        float4 v5 = H[(size_t)cols[c + 5] * 64 + t];
        float4 v6 = H[(size_t)cols[c + 6] * 64 + t];
        float4 v7 = H[(size_t)cols[c + 7] * 64 + t];
        vs.x += ((v0.x + v1.x) + (v2.x + v3.x)) + ((v4.x + v5.x) + (v6.x + v7.x));
        vs.y += ((v0.y + v1.y) + (v2.y + v3.y)) + ((v4.y + v5.y) + (v6.y + v7.y));
        vs.z += ((v0.z + v1.z) + (v2.z + v3.z)) + ((v4.z + v5.z) + (v6.z + v7.z));
        vs.w += ((v0.w + v1.w) + (v2.w + v3.w)) + ((v4.w + v5.w) + (v6.w + v7.w));
    }
    for (; c < hn; c++) {
        float4 v = H[(size_t)cols[c] * 64 + t];
        vs.x += v.x; vs.y += v.y; vs.z += v.z; vs.w += v.w;
    }
    float fd = (float)dn - 1.0f;
    float dot = fd * (h.x * h.x + h.y * h.y + h.z * h.z + h.w * h.w)
              - 2.0f * (h.x * vs.x + h.y * vs.y + h.z * vs.z + h.w * vs.w);
    dot = warpSum(dot);
    __shared__ float sred[8];
    if ((threadIdx.x & 31) == 0) sred[threadIdx.x >> 5] = dot;
    __syncthreads();
    if (threadIdx.x < 4)
        g_partials[blockIdx.x * 4 + threadIdx.x] =
            sred[threadIdx.x * 2] + sred[threadIdx.x * 2 + 1];

    __threadfence();
    __shared__ int isLast;
    if (threadIdx.x == 0) {
        int v = atomicAdd(&g_ctr, 1);
        isLast = (v == (int)gridDim.x - 1) ? 1 : 0;
        if (isLast) atomicExch(&g_ctr, 0);
    }
    __syncthreads();
    if (!isLast) return;
    __threadfence();

    float v = 0.f;
    for (int i = threadIdx.x; i < N; i += 256) v += g_partials[i];
    __shared__ float red2[256];
    red2[threadIdx.x] = v;
    __syncthreads();
    for (int off = 128; off > 0; off >>= 1) {
        if (threadIdx.x < off) red2[threadIdx.x] += red2[threadIdx.x + off];
        __syncthreads();
    }
    if (threadIdx.x == 0) {
        float orth = 0.f;
        for (int p = 0; p < 10; p++) orth += g_orth[p];
        float m = fmaxf(fmaxf(hw[0], hw[1]), fmaxf(hw[2], hw[3]));
        float e0 = expf(hw[0] - m), e1 = expf(hw[1] - m);
        float e2 = expf(hw[2] - m), e3 = expf(hw[3] - m);
        float s = e0 + e1 + e2 + e3;
        int base = N * D;
        if (base < out_size) out[base] = orth;
        if (base + 1 < out_size) out[base + 1] = red2[0];
        if (base + 2 < out_size) out[base + 2] = e0 / s;
        if (base + 3 < out_size) out[base + 3] = e1 / s;
        if (base + 4 < out_size) out[base + 4] = e2 / s;
        if (base + 5 < out_size) out[base + 5] = e3 / s;
    }
}

// ---------------- launch ----------------
extern "C" void kernel_launch(void* const* d_in, const int* in_sizes, int n_in,
                              void* d_out, int out_size) {
    const float* hops      = (const float*)d_in[0];
    const float* adj       = (const float*)d_in[1];
    const float* U         = (const float*)d_in[3];
    const float* hw        = (const float*)d_in[4];
    const float* threshold = (const float*)d_in[5];
    const float* lam       = (const float*)d_in[6];
    float* out = (float*)d_out;

    k_mega1<<<810, 256>>>(hops, adj, U, hw);
    k_gram<<<128, 1024>>>();
    {
        dim3 g(N / 32, K);
        k_MZ<<<g, 256>>>();
    }
    k_attn<<<(K * N) / 8, 256>>>();
    k_lapO<<<N / 8, 256>>>(lam);
    {
        dim3 g(N / 32, D / 32);
        k_HoutG<<<g, 256>>>(hops, threshold, out);
    }
    k_lapF<<<N / 4, 256>>>(out, hw, out, out_size);
}

// round 14
// speedup vs baseline: 1.0609x; 1.0021x over previous
#include <cuda_runtime.h>
#include <math.h>

#define K 4
#define N 4096
#define D 256
#define S 32
#define MAXDEG 512
#define ETA 0.5f
#define COEFF 0.03125f   // S/(N*EPS^2)

// ---------------- scratch ----------------
__device__ float g_Zt[K * N * S];        // [k][n][s]
__device__ float g_MZt[K * N * S];       // [k][n][s]
__device__ float g_Minv[K * S * S];
__device__ float g_O[(size_t)N * (K * S)];   // O_cat: [n][k*S+s]
__device__ float g_O2[(size_t)N * (K * S)];  // (I - lam*L) @ O_cat
__device__ float g_Wc[K * S * D];        // w_k * U[k]^T : [k*S+s][d]
__device__ float g_gramP[K * 32 * S * S];
__device__ int   g_col[(size_t)N * MAXDEG];
__device__ int   g_deg[N];
__device__ float g_partials[N];
__device__ float g_orth[10];
__device__ int   g_ctr;       // zero-init; self-resetting
__device__ int   g_ctrK[K];   // zero-init; self-resetting

__device__ __forceinline__ float warpSum(float v) {
    v += __shfl_xor_sync(0xffffffffu, v, 16);
    v += __shfl_xor_sync(0xffffffffu, v, 8);
    v += __shfl_xor_sync(0xffffffffu, v, 4);
    v += __shfl_xor_sync(0xffffffffu, v, 2);
    v += __shfl_xor_sync(0xffffffffu, v, 1);
    return v;
}

// ================= mega kernel 1: Z (0..255) | CSR (256..767) | Wc (768..799) | orth (800..809) =================
__global__ void __launch_bounds__(256) k_mega1(const float* __restrict__ hops,
                                               const float* __restrict__ adj,
                                               const float* __restrict__ U,
                                               const float* __restrict__ hw) {
    __shared__ float sm[6528];
    int bx = blockIdx.x;
    int tid = threadIdx.x;

    if (bx < 256) {
        // ---------- Z = hops[k] @ U[k] : 64n x 32s tile, double-buffered ----------
        int k = bx >> 6;
        int n0 = (bx & 63) * 64;
        float* hsT0 = sm;            // 32*66
        float* hsT1 = sm + 2112;
        float* us0  = sm + 4224;     // 32*36
        float* us1  = sm + 5376;
        int ny = tid >> 3;
        int sx = (tid & 7) * 4;
        int rowq = tid >> 3;
        int q = tid & 7;
        const float* Hb = hops + ((size_t)k * N + n0) * D;
        const float* Ub = U + (size_t)k * D * S;

        float4 h0, h1, u0;
        h0 = *(const float4*)&Hb[(size_t)rowq * D + q * 4];
        h1 = *(const float4*)&Hb[(size_t)(rowq + 32) * D + q * 4];
        u0 = *(const float4*)&Ub[(size_t)rowq * S + q * 4];
        {
            float* hb = hsT0;
            hb[(q * 4 + 0) * 66 + rowq] = h0.x;
            hb[(q * 4 + 1) * 66 + rowq] = h0.y;
            hb[(q * 4 + 2) * 66 + rowq] = h0.z;
            hb[(q * 4 + 3) * 66 + rowq] = h0.w;
            hb[(q * 4 + 0) * 66 + rowq + 32] = h1.x;
            hb[(q * 4 + 1) * 66 + rowq + 32] = h1.y;
            hb[(q * 4 + 2) * 66 + rowq + 32] = h1.z;
            hb[(q * 4 + 3) * 66 + rowq + 32] = h1.w;
            *(float4*)&us0[rowq * 36 + q * 4] = u0;
        }
        __syncthreads();

        float a0x = 0.f, a0y = 0.f, a0z = 0.f, a0w = 0.f;
        float a1x = 0.f, a1y = 0.f, a1z = 0.f, a1w = 0.f;

        for (int ch = 0; ch < 8; ch++) {
            const float* hb = (ch & 1) ? hsT1 : hsT0;
            const float* ub = (ch & 1) ? us1 : us0;
            if (ch < 7) {
                int dc = (ch + 1) * 32;
                h0 = *(const float4*)&Hb[(size_t)rowq * D + dc + q * 4];
                h1 = *(const float4*)&Hb[(size_t)(rowq + 32) * D + dc + q * 4];
                u0 = *(const float4*)&Ub[(size_t)(dc + rowq) * S + q * 4];
            }
#pragma unroll
            for (int d = 0; d < 32; d++) {
                float2 h = *(const float2*)&hb[d * 66 + ny * 2];
                float4 u = *(const float4*)&ub[d * 36 + sx];
                a0x += h.x * u.x; a0y += h.x * u.y; a0z += h.x * u.z; a0w += h.x * u.w;
                a1x += h.y * u.x; a1y += h.y * u.y; a1z += h.y * u.z; a1w += h.y * u.w;
            }
            if (ch < 7) {
                float* hb2 = (ch & 1) ? hsT0 : hsT1;
                float* ub2 = (ch & 1) ? us0 : us1;
                hb2[(q * 4 + 0) * 66 + rowq] = h0.x;
                hb2[(q * 4 + 1) * 66 + rowq] = h0.y;
                hb2[(q * 4 + 2) * 66 + rowq] = h0.z;
                hb2[(q * 4 + 3) * 66 + rowq] = h0.w;
                hb2[(q * 4 + 0) * 66 + rowq + 32] = h1.x;
                hb2[(q * 4 + 1) * 66 + rowq + 32] = h1.y;
                hb2[(q * 4 + 2) * 66 + rowq + 32] = h1.z;
                hb2[(q * 4 + 3) * 66 + rowq + 32] = h1.w;
                *(float4*)&ub2[rowq * 36 + q * 4] = u0;
            }
            __syncthreads();
        }
        size_t base = ((size_t)k * N + n0 + ny * 2) * S + sx;
        *(float4*)&g_Zt[base] = make_float4(a0x, a0y, a0z, a0w);
        *(float4*)&g_Zt[base + S] = make_float4(a1x, a1y, a1z, a1w);
    } else if (bx < 768) {
        // ---------- CSR build (warp per row, float4 + 4 ballots per 128 cols) ----------
        int n = (bx - 256) * 8 + (tid >> 5);
        int lane = tid & 31;
        const float4* row = (const float4*)(adj + (size_t)n * N);
        int* dst = g_col + (size_t)n * MAXDEG;
        unsigned lm = (1u << lane) - 1u;
        int cnt = 0;
        for (int base = 0; base < N / 4; base += 32) {
            float4 a = row[base + lane];
            unsigned m0 = __ballot_sync(0xffffffffu, a.x != 0.0f);
            unsigned m1 = __ballot_sync(0xffffffffu, a.y != 0.0f);
            unsigned m2 = __ballot_sync(0xffffffffu, a.z != 0.0f);
            unsigned m3 = __ballot_sync(0xffffffffu, a.w != 0.0f);
            int pre = cnt + __popc(m0 & lm) + __popc(m1 & lm)
                          + __popc(m2 & lm) + __popc(m3 & lm);
            int j0 = (base + lane) * 4;
            if (a.x != 0.0f) dst[pre] = j0;
            int o1 = pre + ((m0 >> lane) & 1);
            if (a.y != 0.0f) dst[o1] = j0 + 1;
            int o2 = o1 + ((m1 >> lane) & 1);
            if (a.z != 0.0f) dst[o2] = j0 + 2;
            int o3 = o2 + ((m2 >> lane) & 1);
            if (a.w != 0.0f) dst[o3] = j0 + 3;
            cnt += __popc(m0) + __popc(m1) + __popc(m2) + __popc(m3);
        }
        if (lane == 0) g_deg[n] = min(cnt, MAXDEG);
    } else if (bx < 800) {
        // ---------- Wc[k*S+s][d] = w_k * U[k][d][s] ----------
        float m = fmaxf(fmaxf(hw[0], hw[1]), fmaxf(hw[2], hw[3]));
        float e0 = expf(hw[0] - m), e1 = expf(hw[1] - m);
        float e2 = expf(hw[2] - m), e3 = expf(hw[3] - m);
        float sum = e0 + e1 + e2 + e3;
        int base = ((bx - 768) * 256 + tid) * 4;
        float4 u4 = *(const float4*)&U[base];
        int k = base / (D * S);
        int rem = base % (D * S);
        int d = rem / S;
        int s = rem % S;
        float wk = (k == 0 ? e0 : k == 1 ? e1 : k == 2 ? e2 : e3) / sum;
        g_Wc[(k * S + s + 0) * D + d] = wk * u4.x;
        g_Wc[(k * S + s + 1) * D + d] = wk * u4.y;
        g_Wc[(k * S + s + 2) * D + d] = wk * u4.z;
        g_Wc[(k * S + s + 3) * D + d] = wk * u4.w;
    } else {
        // ---------- orth pair (s,t) dots; 4 t per thread ----------
        const int kk[10] = {0, 0, 0, 0, 1, 1, 1, 2, 2, 3};
        const int ll[10] = {0, 1, 2, 3, 1, 2, 3, 2, 3, 3};
        int p = bx - 800;
        int k = kk[p], l = ll[p];
        int s = tid >> 3;
        int t0 = (tid & 7) * 4;
        float* uk = sm;
        float* ul = sm + 2048;
        float* red = sm + 4096;
        float c0 = 0.f, c1 = 0.f, c2 = 0.f, c3 = 0.f;
        for (int dc = 0; dc < D; dc += 64) {
            for (int i = tid; i < 2048; i += 256) {
                uk[i] = U[((size_t)k * D + dc) * S + i];
                ul[i] = U[((size_t)l * D + dc) * S + i];
            }
            __syncthreads();
#pragma unroll 8
            for (int d = 0; d < 64; d++) {
                float a = uk[d * 32 + s];
                float4 b = *(const float4*)&ul[d * 32 + t0];
                c0 += a * b.x; c1 += a * b.y; c2 += a * b.z; c3 += a * b.w;
            }
            __syncthreads();
        }
        if (k == l) {
            if (s == t0 + 0) c0 -= 1.0f;
            if (s == t0 + 1) c1 -= 1.0f;
            if (s == t0 + 2) c2 -= 1.0f;
            if (s == t0 + 3) c3 -= 1.0f;
        }
        red[tid] = (c0 * c0 + c1 * c1) + (c2 * c2 + c3 * c3);
        __syncthreads();
        for (int off = 128; off > 0; off >>= 1) {
            if (tid < off) red[tid] += red[tid + off];
            __syncthreads();
        }
        if (tid == 0) g_orth[p] = red[0];
    }
}

// ================= gram partials + last-block-per-k inversion =================
__global__ void __launch_bounds__(1024) k_gram(void) {
    __shared__ float sm[4224];
    int tid = threadIdx.x;
    int k = blockIdx.x >> 5;
    int chunk = blockIdx.x & 31;
    float* zs = sm;
    const float4* Z4 = (const float4*)(g_Zt + ((size_t)k * N + chunk * 128) * S);
    ((float4*)zs)[tid] = Z4[tid];
    __syncthreads();
    int s = tid >> 5, t = tid & 31;
    float g0 = 0.f, g1 = 0.f, g2 = 0.f, g3 = 0.f;
#pragma unroll 8
    for (int n = 0; n < 128; n += 4) {
        g0 += zs[(n + 0) * 32 + s] * zs[(n + 0) * 32 + t];
        g1 += zs[(n + 1) * 32 + s] * zs[(n + 1) * 32 + t];
        g2 += zs[(n + 2) * 32 + s] * zs[(n + 2) * 32 + t];
        g3 += zs[(n + 3) * 32 + s] * zs[(n + 3) * 32 + t];
    }
    g_gramP[(((size_t)k * 32 + chunk) * S + s) * S + t] = (g0 + g1) + (g2 + g3);
    __threadfence();
    __shared__ int isLast;
    if (tid == 0) {
        int v = atomicAdd(&g_ctrK[k], 1);
        isLast = (v == 31);
        if (v == 31) atomicExch(&g_ctrK[k], 0);
    }
    __syncthreads();
    if (!isLast) return;
    __threadfence();
    float g = 0.f;
    for (int c = 0; c < 32; c++)
        g += g_gramP[(((size_t)k * 32 + c) * S + s) * S + t];
    float (*aug)[66] = (float(*)[66])sm;
    __syncthreads();
    aug[s][t] = (s == t ? 1.0f : 0.0f) + COEFF * g;
    aug[s][32 + t] = (s == t ? 1.0f : 0.0f);
    __syncthreads();
    int r0 = tid >> 6, c0 = tid & 63;
    int tid2 = tid + 1024;
    int r1 = tid2 >> 6, c1 = tid2 & 63;
    for (int p = 0; p < 32; p++) {
        float inv = 1.0f / aug[p][p];
        float f0 = aug[r0][p], pr0 = aug[p][c0];
        float f1 = aug[r1][p], pr1 = aug[p][c1];
        __syncthreads();
        if (r0 == p) aug[p][c0] = pr0 * inv;
        else         aug[r0][c0] -= f0 * inv * pr0;
        if (r1 == p) aug[p][c1] = pr1 * inv;
        else         aug[r1][c1] -= f1 * inv * pr1;
        __syncthreads();
    }
    g_Minv[k * S * S + s * S + t] = aug[s][32 + t];
}

// ================= MZt = Minv[k] @ Zt rows : conflict-free, 4 rows/warp =================
__global__ void k_MZ(void) {
    __shared__ float Msh[32 * 33];
    __shared__ float zsh[32 * 33];
    int k = blockIdx.y;
    int n0 = blockIdx.x * 32;
    int tid = threadIdx.x;
    int w = tid >> 5;
    int lane = tid & 31;
    {
        float4 v = ((const float4*)(g_Minv + k * S * S))[tid];
        int r = (tid * 4) >> 5;
        int c = (tid * 4) & 31;
        float* dst = &Msh[r * 33 + c];
        dst[0] = v.x; dst[1] = v.y; dst[2] = v.z; dst[3] = v.w;
    }
    {
        int r = tid >> 3, q = tid & 7;
        float4 v = *(const float4*)&g_Zt[((size_t)k * N + n0 + r) * S + q * 4];
        float* dst = &zsh[r * 33 + q * 4];
        dst[0] = v.x; dst[1] = v.y; dst[2] = v.z; dst[3] = v.w;
    }
    __syncthreads();
    float a0 = 0.f, a1 = 0.f, a2 = 0.f, a3 = 0.f;
    const float* z0 = &zsh[(w * 4 + 0) * 33];
    const float* z1 = &zsh[(w * 4 + 1) * 33];
    const float* z2 = &zsh[(w * 4 + 2) * 33];
    const float* z3 = &zsh[(w * 4 + 3) * 33];
#pragma unroll
    for (int t = 0; t < 32; t++) {
        float mv = Msh[t * 33 + lane];
        a0 += mv * z0[t];
        a1 += mv * z1[t];
        a2 += mv * z2[t];
        a3 += mv * z3[t];
    }
    size_t base = ((size_t)k * N + n0 + w * 4) * S + lane;
    g_MZt[base] = a0;
    g_MZt[base + S] = a1;
    g_MZt[base + 2 * S] = a2;
    g_MZt[base + 3 * S] = a3;
}

// ================= sparse attention: 4 lanes/row, 4 independent chains (32 rows/iter) =================
__global__ void __launch_bounds__(256) k_attn(void) {
    int w = threadIdx.x >> 5;
    int lane = threadIdx.x & 31;
    int gwarp = blockIdx.x * 8 + w;
    int k = gwarp >> 12;
    int n = gwarp & (N - 1);
    const float* __restrict__ MZ = g_MZt + (size_t)k * N * S;
    const int* __restrict__ cols = g_col + (size_t)n * MAXDEG;
    int dn = g_deg[n];
    int f2 = lane & 3;
    int rr = lane >> 2;
    const float LOG2E = 1.4426950408889634f;
    const float* qp = &g_Zt[((size_t)k * N + n) * S + f2 * 8];
    float4 qa = *(const float4*)&qp[0];
    float4 qb = *(const float4*)&qp[4];
    qa.x *= LOG2E; qa.y *= LOG2E; qa.z *= LOG2E; qa.w *= LOG2E;
    qb.x *= LOG2E; qb.y *= LOG2E; qb.z *= LOG2E; qb.w *= LOG2E;

    float4 aa = make_float4(0.f, 0.f, 0.f, 0.f);
    float4 ab = make_float4(0.f, 0.f, 0.f, 0.f);
    float l = 0.f;

    // prologue: indices for chunk 0 (4 chains)
    int j0 = (rr < dn) ? cols[rr] : 0;
    int j1 = (8 + rr < dn) ? cols[8 + rr] : 0;
    int j2 = (16 + rr < dn) ? cols[16 + rr] : 0;
    int j3 = (24 + rr < dn) ? cols[24 + rr] : 0;

    for (int c0 = 0; c0 < dn; c0 += 32) {
        // issue 8 independent LDG.128 for this iteration's 4 rows x 2 halves
        const float* vp0 = &MZ[(size_t)j0 * S + f2 * 8];
        const float* vp1 = &MZ[(size_t)j1 * S + f2 * 8];
        const float* vp2 = &MZ[(size_t)j2 * S + f2 * 8];
        const float* vp3 = &MZ[(size_t)j3 * S + f2 * 8];
        float4 va0 = *(const float4*)&vp0[0];
        float4 vb0 = *(const float4*)&vp0[4];
        float4 va1 = *(const float4*)&vp1[0];
        float4 vb1 = *(const float4*)&vp1[4];
        float4 va2 = *(const float4*)&vp2[0];
        float4 vb2 = *(const float4*)&vp2[4];
        float4 va3 = *(const float4*)&vp3[0];
        float4 vb3 = *(const float4*)&vp3[4];
        // prefetch next iteration's indices (overlaps v latency)
        int b0 = c0 + 32 + rr;
        int jn0 = (b0 < dn) ? cols[b0] : 0;
        int jn1 = (b0 + 8 < dn) ? cols[b0 + 8] : 0;
        int jn2 = (b0 + 16 < dn) ? cols[b0 + 16] : 0;
        int jn3 = (b0 + 24 < dn) ? cols[b0 + 24] : 0;

        float p0 = qa.x * va0.x + qa.y * va0.y + qa.z * va0.z + qa.w * va0.w
                 + qb.x * vb0.x + qb.y * vb0.y + qb.z * vb0.z + qb.w * vb0.w;
        float p1 = qa.x * va1.x + qa.y * va1.y + qa.z * va1.z + qa.w * va1.w
                 + qb.x * vb1.x + qb.y * vb1.y + qb.z * vb1.z + qb.w * vb1.w;
        float p2 = qa.x * va2.x + qa.y * va2.y + qa.z * va2.z + qa.w * va2.w
                 + qb.x * vb2.x + qb.y * vb2.y + qb.z * vb2.z + qb.w * vb2.w;
        float p3 = qa.x * va3.x + qa.y * va3.y + qa.z * va3.z + qa.w * va3.w
                 + qb.x * vb3.x + qb.y * vb3.y + qb.z * vb3.z + qb.w * vb3.w;
        p0 += __shfl_xor_sync(0xffffffffu, p0, 1);
        p1 += __shfl_xor_sync(0xffffffffu, p1, 1);
        p2 += __shfl_xor_sync(0xffffffffu, p2, 1);
        p3 += __shfl_xor_sync(0xffffffffu, p3, 1);
        p0 += __shfl_xor_sync(0xffffffffu, p0, 2);
        p1 += __shfl_xor_sync(0xffffffffu, p1, 2);
        p2 += __shfl_xor_sync(0xffffffffu, p2, 2);
        p3 += __shfl_xor_sync(0xffffffffu, p3, 2);
        p0 = (c0 + rr < dn) ? p0 : -1e30f;
        p1 = (c0 + 8 + rr < dn) ? p1 : -1e30f;
        p2 = (c0 + 16 + rr < dn) ? p2 : -1e30f;
        p3 = (c0 + 24 + rr < dn) ? p3 : -1e30f;
        float e0 = exp2f(p0);
        float e1 = exp2f(p1);
        float e2 = exp2f(p2);
        float e3 = exp2f(p3);
        l += (e0 + e1) + (e2 + e3);
        aa.x += e0 * va0.x + e1 * va1.x + e2 * va2.x + e3 * va3.x;
        aa.y += e0 * va0.y + e1 * va1.y + e2 * va2.y + e3 * va3.y;
        aa.z += e0 * va0.z + e1 * va1.z + e2 * va2.z + e3 * va3.z;
        aa.w += e0 * va0.w + e1 * va1.w + e2 * va2.w + e3 * va3.w;
        ab.x += e0 * vb0.x + e1 * vb1.x + e2 * vb2.x + e3 * vb3.x;
        ab.y += e0 * vb0.y + e1 * vb1.y + e2 * vb2.y + e3 * vb3.y;
        ab.z += e0 * vb0.z + e1 * vb1.z + e2 * vb2.z + e3 * vb3.z;
        ab.w += e0 * vb0.w + e1 * vb1.w + e2 * vb2.w + e3 * vb3.w;

        j0 = jn0; j1 = jn1; j2 = jn2; j3 = jn3;
    }

    // fold across the 8 rr-groups (xor 4, 8, 16)
#pragma unroll
    for (int off = 4; off <= 16; off <<= 1) {
        aa.x += __shfl_xor_sync(0xffffffffu, aa.x, off);
        aa.y += __shfl_xor_sync(0xffffffffu, aa.y, off);
        aa.z += __shfl_xor_sync(0xffffffffu, aa.z, off);
        aa.w += __shfl_xor_sync(0xffffffffu, aa.w, off);
        ab.x += __shfl_xor_sync(0xffffffffu, ab.x, off);
        ab.y += __shfl_xor_sync(0xffffffffu, ab.y, off);
        ab.z += __shfl_xor_sync(0xffffffffu, ab.z, off);
        ab.w += __shfl_xor_sync(0xffffffffu, ab.w, off);
        l    += __shfl_xor_sync(0xffffffffu, l, off);
    }
    if (rr == 0) {
        float inv = 1.0f / l;
        float* dst = &g_O[(size_t)n * (K * S) + k * S + f2 * 8];
        *(float4*)&dst[0] = make_float4(aa.x * inv, aa.y * inv, aa.z * inv, aa.w * inv);
        *(float4*)&dst[4] = make_float4(ab.x * inv, ab.y * inv, ab.z * inv, ab.w * inv);
    }
}

// ================= O2 = (I - lam*L) @ O_cat : 8-wide MLP gather =================
__global__ void k_lapO(const float* __restrict__ lambda_lap) {
    int n = blockIdx.x * 8 + (threadIdx.x >> 5);
    int lane = threadIdx.x & 31;
    const float4* O = (const float4*)g_O;
    const int* cols = g_col + (size_t)n * MAXDEG;
    int dn = g_deg[n];
    float4 o = O[(size_t)n * 32 + lane];
    float4 s = make_float4(0.f, 0.f, 0.f, 0.f);
    int c = 0;
    for (; c + 8 <= dn; c += 8) {
        float4 v0 = O[(size_t)cols[c] * 32 + lane];
        float4 v1 = O[(size_t)cols[c + 1] * 32 + lane];
        float4 v2 = O[(size_t)cols[c + 2] * 32 + lane];
        float4 v3 = O[(size_t)cols[c + 3] * 32 + lane];
        float4 v4 = O[(size_t)cols[c + 4] * 32 + lane];
        float4 v5 = O[(size_t)cols[c + 5] * 32 + lane];
        float4 v6 = O[(size_t)cols[c + 6] * 32 + lane];
        float4 v7 = O[(size_t)cols[c + 7] * 32 + lane];
        s.x += ((v0.x + v1.x) + (v2.x + v3.x)) + ((v4.x + v5.x) + (v6.x + v7.x));
        s.y += ((v0.y + v1.y) + (v2.y + v3.y)) + ((v4.y + v5.y) + (v6.y + v7.y));
        s.z += ((v0.z + v1.z) + (v2.z + v3.z)) + ((v4.z + v5.z) + (v6.z + v7.z));
        s.w += ((v0.w + v1.w) + (v2.w + v3.w)) + ((v4.w + v5.w) + (v6.w + v7.w));
    }
    for (; c < dn; c++) {
        float4 v = O[(size_t)cols[c] * 32 + lane];
        s.x += v.x; s.y += v.y; s.z += v.z; s.w += v.w;
    }
    float lam = lambda_lap[0];
    float fd = (float)dn;
    float4 r;
    r.x = o.x - lam * (fd * o.x - s.x);
    r.y = o.y - lam * (fd * o.y - s.y);
    r.z = o.z - lam * (fd * o.z - s.z);
    r.w = o.w - lam * (fd * o.w - s.w);
    ((float4*)g_O2)[(size_t)n * 32 + lane] = r;
}

// ================= H_out = softthresh(hops0 + ETA * O2 @ Wc) =================
__global__ void k_HoutG(const float* __restrict__ hops,
                        const float* __restrict__ threshold,
                        float* __restrict__ out) {
    __shared__ float as[32][33];
    __shared__ float ws[32][33];
    int n0 = blockIdx.x * 32, d0 = blockIdx.y * 32;
    int lane = threadIdx.x & 31;
    int row = threadIdx.x >> 5;
    float acc[4] = {0.f, 0.f, 0.f, 0.f};
    for (int cc = 0; cc < K * S; cc += 32) {
#pragma unroll
        for (int i = 0; i < 4; i++) {
            int r = row + i * 8;
            as[r][lane] = g_O2[(size_t)(n0 + r) * (K * S) + cc + lane];
            ws[r][lane] = g_Wc[(size_t)(cc + r) * D + d0 + lane];
        }
        __syncthreads();
#pragma unroll
        for (int dd = 0; dd < 32; dd++) {
            float wv = ws[dd][lane];
#pragma unroll
            for (int i = 0; i < 4; i++) acc[i] += as[row * 4 + i][dd] * wv;
        }
        __syncthreads();
    }
    float th = threshold[d0 + lane];
#pragma unroll
    for (int i = 0; i < 4; i++) {
        int n = n0 + row * 4 + i;
        float hh = hops[(size_t)n * D + d0 + lane] + ETA * acc[i];
        float ab = fabsf(hh) - th;
        out[(size_t)n * D + d0 + lane] = (ab > 0.f) ? copysignf(ab, hh) : 0.f;
    }
}

// ================= lap_smooth partials (symmetric half, 8-wide MLP) + fused final =================
__global__ void k_lapF(const float* __restrict__ Hout, const float* __restrict__ hw,
                       float* __restrict__ out, int out_size) {
    __shared__ int hd[4];
    if (threadIdx.x < 4) {
        int nn = blockIdx.x * 4 + threadIdx.x;
        const int* cc = g_col + (size_t)nn * MAXDEG;
        int lo = 0, hi = g_deg[nn];
        while (lo < hi) {
            int mid = (lo + hi) >> 1;
            if (cc[mid] < nn) lo = mid + 1; else hi = mid;
        }
        hd[threadIdx.x] = lo;
    }
    __syncthreads();
    int g = threadIdx.x >> 6;
    int n = blockIdx.x * 4 + g;
    int t = threadIdx.x & 63;
    const float4* H = (const float4*)Hout;
    const int* cols = g_col + (size_t)n * MAXDEG;
    int dn = g_deg[n];
    int hn = hd[g];
    float4 h = H[(size_t)n * 64 + t];
    float4 vs = make_float4(0.f, 0.f, 0.f, 0.f);
    int c = 0;
    for (; c + 8 <= hn; c += 8) {
        float4 v0 = H[(size_t)cols[c] * 64 + t];
        float4 v1 = H[(size_t)cols[c + 1] * 64 + t];
        float4 v2 = H[(size_t)cols[c + 2] * 64 + t];
        float4 v3 = H[(size_t)cols[c + 3] * 64 + t];
        float4 v4 = H[(size_t)cols[c + 4] * 64 + t];
        float4 v5 = H[(size_t)cols[c + 5] * 64 + t];
        float4 v6 = H[(size_t)cols[c + 6] * 64 + t];
        float4 v7 = H[(size_t)cols[c + 7] * 64 + t];
        vs.x += ((v0.x + v1.x) + (v2.x + v3.x)) + ((v4.x + v5.x) + (v6.x + v7.x));
        vs.y += ((v0.y + v1.y) + (v2.y + v3.y)) + ((v4.y + v5.y) + (v6.y + v7.y));
        vs.z += ((v0.z + v1.z) + (v2.z + v3.z)) + ((v4.z + v5.z) + (v6.z + v7.z));
        vs.w += ((v0.w + v1.w) + (v2.w + v3.w)) + ((v4.w + v5.w) + (v6.w + v7.w));
    }
    for (; c < hn; c++) {
        float4 v = H[(size_t)cols[c] * 64 + t];
        vs.x += v.x; vs.y += v.y; vs.z += v.z; vs.w += v.w;
    }
    float fd = (float)dn - 1.0f;
    float dot = fd * (h.x * h.x + h.y * h.y + h.z * h.z + h.w * h.w)
              - 2.0f * (h.x * vs.x + h.y * vs.y + h.z * vs.z + h.w * vs.w);
    dot = warpSum(dot);
    __shared__ float sred[8];
    if ((threadIdx.x & 31) == 0) sred[threadIdx.x >> 5] = dot;
    __syncthreads();
    if (threadIdx.x < 4)
        g_partials[blockIdx.x * 4 + threadIdx.x] =
            sred[threadIdx.x * 2] + sred[threadIdx.x * 2 + 1];

    __threadfence();
    __shared__ int isLast;
    if (threadIdx.x == 0) {
        int v = atomicAdd(&g_ctr, 1);
        isLast = (v == (int)gridDim.x - 1) ? 1 : 0;
        if (isLast) atomicExch(&g_ctr, 0);
    }
    __syncthreads();
    if (!isLast) return;
    __threadfence();

    float v = 0.f;
    for (int i = threadIdx.x; i < N; i += 256) v += g_partials[i];
    __shared__ float red2[256];
    red2[threadIdx.x] = v;
    __syncthreads();
    for (int off = 128; off > 0; off >>= 1) {
        if (threadIdx.x < off) red2[threadIdx.x] += red2[threadIdx.x + off];
        __syncthreads();
    }
    if (threadIdx.x == 0) {
        float orth = 0.f;
        for (int p = 0; p < 10; p++) orth += g_orth[p];
        float m = fmaxf(fmaxf(hw[0], hw[1]), fmaxf(hw[2], hw[3]));
        float e0 = expf(hw[0] - m), e1 = expf(hw[1] - m);
        float e2 = expf(hw[2] - m), e3 = expf(hw[3] - m);
        float s = e0 + e1 + e2 + e3;
        int base = N * D;
        if (base < out_size) out[base] = orth;
        if (base + 1 < out_size) out[base + 1] = red2[0];
        if (base + 2 < out_size) out[base + 2] = e0 / s;
        if (base + 3 < out_size) out[base + 3] = e1 / s;
        if (base + 4 < out_size) out[base + 4] = e2 / s;
        if (base + 5 < out_size) out[base + 5] = e3 / s;
    }
}

// ---------------- launch ----------------
extern "C" void kernel_launch(void* const* d_in, const int* in_sizes, int n_in,
                              void* d_out, int out_size) {
    const float* hops      = (const float*)d_in[0];
    const float* adj       = (const float*)d_in[1];
    const float* U         = (const float*)d_in[3];
    const float* hw        = (const float*)d_in[4];
    const float* threshold = (const float*)d_in[5];
    const float* lam       = (const float*)d_in[6];
    float* out = (float*)d_out;

    k_mega1<<<810, 256>>>(hops, adj, U, hw);
    k_gram<<<128, 1024>>>();
    {
        dim3 g(N / 32, K);
        k_MZ<<<g, 256>>>();
    }
    k_attn<<<(K * N) / 8, 256>>>();
    k_lapO<<<N / 8, 256>>>(lam);
    {
        dim3 g(N / 32, D / 32);
        k_HoutG<<<g, 256>>>(hops, threshold, out);
    }
    k_lapF<<<N / 4, 256>>>(out, hw, out, out_size);
}